// round 16
// baseline (speedup 1.0000x reference)
#include <cuda_runtime.h>
#include <cstdint>

#define FH   45
#define FW   80
#define CC   64
#define BB   16
#define NN   2784
#define JOUT 75
#define JP   80          // P padded j-dim (20 float4)
#define ODIM 77

__device__ float  g_F[BB * CC * FH * FW];    // feat[b][o][h][w], 14.75 MB
__device__ float4 g_P[BB * FH * FW * (JP/4)];// P[b][h][w][j/4], 18.4 MB
__device__ int    g_off[NN * FH];            // compacted valid offsets per anchor
__device__ int    g_cnt[NN];                 // valid count per anchor

// ---------- f32x2 helpers (sm_103a packed fp32) ----------
__device__ __forceinline__ unsigned long long pack2(float a, float b) {
    unsigned long long r;
    asm("mov.b64 %0, {%1, %2};" : "=l"(r) : "f"(a), "f"(b));
    return r;
}
__device__ __forceinline__ void unpack2(unsigned long long v, float& a, float& b) {
    asm("mov.b64 {%0, %1}, %2;" : "=f"(a), "=f"(b) : "l"(v));
}
__device__ __forceinline__ unsigned long long fma2(unsigned long long a,
                                                   unsigned long long b,
                                                   unsigned long long c) {
    unsigned long long r;
    asm("fma.rn.f32x2 %0, %1, %2, %3;" : "=l"(r) : "l"(a), "l"(b), "l"(c));
    return r;
}

// ---------------------------------------------------------------------------
// k_feat: feat[b,o,h,w] = sum_ci conv_w[o,ci]*x[b,ci,h,w] + conv_b[o]
// grid (FH, BB+1), block (20,16)=320. blockIdx.y==BB: anchor compaction.
// Thread tile: 4 w (float4) x 4 o, f32x2 along w.
// ---------------------------------------------------------------------------
__global__ void k_feat(const float* __restrict__ x,
                       const float* __restrict__ conv_w, const float* __restrict__ conv_b,
                       const int* __restrict__ cut_xs,
                       const unsigned char* __restrict__ invalid) {
    int tid = threadIdx.y * 20 + threadIdx.x;   // 0..319

    if (blockIdx.y == BB) {
        int n = blockIdx.x * 320 + tid;
        if (n >= NN) return;
        const int* cx = cut_xs + n * FH;
        const unsigned char* iv = invalid + n * FH;
        int c = 0;
        int* on = g_off + n * FH;
#pragma unroll 9
        for (int h = 0; h < FH; h++) {
            int xv = cx[h];
            xv = min(max(xv, 0), FW - 1);
            if (!iv[h]) on[c++] = (h * FW + xv) * (JP / 4);
        }
        g_cnt[n] = c;
        return;
    }

    int h = blockIdx.x, b = blockIdx.y;
    __shared__ float sx[CC][FW];        // x[b][ci][h][w]
    __shared__ float sc[CC][CC + 1];    // conv_w[o][ci], padded
    __shared__ float sb[CC];

    {
        const float4* xb4 = (const float4*)(x + ((size_t)(b * CC) * FH + h) * FW);
        float4* sx4 = (float4*)&sx[0][0];
#pragma unroll
        for (int i = tid; i < CC * FW / 4; i += 320) {
            int ci = i / 20, w4 = i - ci * 20;
            sx4[i] = xb4[(size_t)ci * (FH * FW / 4) + w4];
        }
        const float4* cw4 = (const float4*)conv_w;
        for (int i = tid; i < CC * CC / 4; i += 320) {
            int o = i >> 4, c4 = (i & 15) * 4;
            float4 v = cw4[i];
            sc[o][c4 + 0] = v.x; sc[o][c4 + 1] = v.y;
            sc[o][c4 + 2] = v.z; sc[o][c4 + 3] = v.w;
        }
        if (tid < CC) sb[tid] = conv_b[tid];
    }
    __syncthreads();

    int w0 = threadIdx.x * 4;   // 20*4 = 80
    int o0 = threadIdx.y * 4;   // 16*4 = 64
    unsigned long long acc[4][2];
    unsigned long long z = pack2(0.f, 0.f);
#pragma unroll
    for (int k = 0; k < 4; k++) { acc[k][0] = z; acc[k][1] = z; }

#pragma unroll 4
    for (int ci = 0; ci < CC; ci++) {
        unsigned long long xa = *(const unsigned long long*)&sx[ci][w0];
        unsigned long long xb = *(const unsigned long long*)&sx[ci][w0 + 2];
#pragma unroll
        for (int k = 0; k < 4; k++) {
            float wv = sc[o0 + k][ci];
            unsigned long long pw = pack2(wv, wv);
            acc[k][0] = fma2(xa, pw, acc[k][0]);
            acc[k][1] = fma2(xb, pw, acc[k][1]);
        }
    }

    float* Fb = g_F + ((size_t)(b * CC) * FH + h) * FW;
#pragma unroll
    for (int k = 0; k < 4; k++) {
        float bo = sb[o0 + k];
        float4 r;
        float p0, p1;
        unpack2(acc[k][0], p0, p1); r.x = p0 + bo; r.y = p1 + bo;
        unpack2(acc[k][1], p0, p1); r.z = p0 + bo; r.w = p1 + bo;
        *(float4*)&Fb[(size_t)(o0 + k) * FH * FW + w0] = r;
    }
}

// ---------------------------------------------------------------------------
// k_mid: P[b,h,w,j] = sum_o feat[b,o,h,w]*Wcat[o,h,j]   (no bias; k3 adds it)
// block (20,16): 4j x 5w tile per thread. grid (FH, BB).
// ---------------------------------------------------------------------------
__global__ void k_pcompute(const float* __restrict__ cls_w, const float* __restrict__ reg_w) {
    int h = blockIdx.x, b = blockIdx.y;
    __shared__ float sx[CC][FW];   // feat[b][o][h][w]
    __shared__ float sw[CC][JP];   // Wcat[o][j]
    int tid = threadIdx.y * 20 + threadIdx.x;   // 0..319

    {
        const float4* fb4 = (const float4*)(g_F + ((size_t)(b * CC) * FH + h) * FW);
        float4* sx4 = (float4*)&sx[0][0];
#pragma unroll
        for (int i = tid; i < CC * FW / 4; i += 320) {
            int o = i / 20, w4 = i - o * 20;
            sx4[i] = fb4[(size_t)o * (FH * FW / 4) + w4];
        }
        for (int t = tid; t < CC * JP; t += 320) {
            int o = t / JP, j = t - o * JP;
            float v = 0.f;
            if (j < 2)          v = cls_w[(o * FH + h) * 2 + j];
            else if (j < JOUT)  v = reg_w[(o * FH + h) * 73 + (j - 2)];
            sw[o][j] = v;
        }
    }
    __syncthreads();

    int j0 = threadIdx.x * 4;   // 20*4 = 80 j
    int w0 = threadIdx.y * 5;   // 16*5 = 80 w
    unsigned long long acc0[5], acc1[5];
    unsigned long long z = pack2(0.f, 0.f);
#pragma unroll
    for (int v = 0; v < 5; v++) { acc0[v] = z; acc1[v] = z; }

#pragma unroll 4
    for (int o = 0; o < CC; o++) {
        unsigned long long wa = *(const unsigned long long*)&sw[o][j0];
        unsigned long long wb = *(const unsigned long long*)&sw[o][j0 + 2];
#pragma unroll
        for (int v = 0; v < 5; v++) {
            float xs = sx[o][w0 + v];
            unsigned long long xv = pack2(xs, xs);
            acc0[v] = fma2(xv, wa, acc0[v]);
            acc1[v] = fma2(xv, wb, acc1[v]);
        }
    }

    float* Pp = (float*)g_P + (size_t)((b * FH + h) * FW) * JP;
#pragma unroll
    for (int v = 0; v < 5; v++) {
        float4 r;
        float p0, p1;
        unpack2(acc0[v], p0, p1); r.x = p0; r.y = p1;
        unpack2(acc1[v], p0, p1); r.z = p0; r.w = p1;
        *(float4*)&Pp[(w0 + v) * JP + j0] = r;
    }
}

// ---------------------------------------------------------------------------
// k3: direct L2 gather, 4 batch-images per block (b, b+4, b+8, b+12).
// block (19,16): 16 anchors x 19 float4 j-lanes. grid (NN/16, 4).
// ---------------------------------------------------------------------------
__global__ void __launch_bounds__(304, 3)
k_gather(const float* __restrict__ cls_b, const float* __restrict__ reg_b,
         const float* __restrict__ anchors,
         float* __restrict__ out) {
    int n0 = blockIdx.x * 16;
    int bb = blockIdx.y;           // 0..3
    __shared__ int offs[16][FH];
    __shared__ int cnt[16];

    int tx  = threadIdx.x;      // 0..18
    int a   = threadIdx.y;      // 0..15
    int tid = a * 19 + tx;
    for (int t = tid; t < 16 * FH; t += 304) {
        int aa = t / FH, hh = t - aa * FH;
        offs[aa][hh] = g_off[(n0 + aa) * FH + hh];
    }
    if (tid < 16) cnt[tid] = g_cnt[n0 + tid];
    __syncthreads();

    int n = n0 + a;
    const float4* Pb[4];
#pragma unroll
    for (int s = 0; s < 4; s++)
        Pb[s] = g_P + (size_t)(bb + 4 * s) * FH * FW * (JP / 4);

    int jb = tx * 4;
    float bias[4];
#pragma unroll
    for (int u = 0; u < 4; u++) {
        int j = jb + u;
        bias[u] = (j < 2) ? cls_b[j] : ((j < JOUT) ? reg_b[j - 2] : 0.f);
    }
    float av[4][4];
#pragma unroll
    for (int s = 0; s < 4; s++)
#pragma unroll
        for (int u = 0; u < 4; u++) av[s][u] = bias[u];

    int c = cnt[a];
    int i = 0;
    for (; i + 2 <= c; i += 2) {
        int o0 = offs[a][i + 0] + tx;
        int o1 = offs[a][i + 1] + tx;
        float4 p[4], q[4];
#pragma unroll
        for (int s = 0; s < 4; s++) { p[s] = Pb[s][o0]; q[s] = Pb[s][o1]; }
#pragma unroll
        for (int s = 0; s < 4; s++) {
            av[s][0] += p[s].x + q[s].x;
            av[s][1] += p[s].y + q[s].y;
            av[s][2] += p[s].z + q[s].z;
            av[s][3] += p[s].w + q[s].w;
        }
    }
    if (i < c) {
        int o = offs[a][i] + tx;
#pragma unroll
        for (int s = 0; s < 4; s++) {
            float4 p = Pb[s][o];
            av[s][0] += p.x; av[s][1] += p.y; av[s][2] += p.z; av[s][3] += p.w;
        }
    }

    const float* an = anchors + n * ODIM;
    float a2v = an[2], a3v = an[3];
    float anj[4];
#pragma unroll
    for (int u = 0; u < 4; u++) {
        int j = jb + u;
        anj[u] = (j >= 2 && j < JOUT) ? an[j + 2] : 0.f;
    }

#pragma unroll
    for (int s = 0; s < 4; s++) {
        int b = bb + 4 * s;
        int obase = (b * NN + n) * ODIM;
#pragma unroll
        for (int u = 0; u < 4; u++) {
            int j = jb + u;
            if (j < 2)          out[obase + j]     = av[s][u];
            else if (j < JOUT)  out[obase + j + 2] = anj[u] + av[s][u];
        }
        if (tx == 0) {
            out[obase + 2] = a2v;
            out[obase + 3] = a3v;
        }
    }
}

// ---------------------------------------------------------------------------
extern "C" void kernel_launch(void* const* d_in, const int* in_sizes, int n_in,
                              void* d_out, int out_size) {
    const float* x       = (const float*)d_in[0];
    const float* conv_w  = (const float*)d_in[1];
    const float* conv_b  = (const float*)d_in[2];
    const float* cls_w   = (const float*)d_in[3];
    const float* cls_b   = (const float*)d_in[4];
    const float* reg_w   = (const float*)d_in[5];
    const float* reg_b   = (const float*)d_in[6];
    const float* anchors = (const float*)d_in[7];
    const int*   cut_xs  = (const int*)d_in[8];
    const unsigned char* invalid = (const unsigned char*)d_in[9];
    float* out = (float*)d_out;

    k_feat    <<<dim3(FH, BB + 1), dim3(20, 16)>>>(x, conv_w, conv_b, cut_xs, invalid);
    k_pcompute<<<dim3(FH, BB),     dim3(20, 16)>>>(cls_w, reg_w);
    k_gather  <<<dim3(NN / 16, 4), dim3(19, 16)>>>(cls_b, reg_b, anchors, out);
}

// round 17
// speedup vs baseline: 1.6199x; 1.6199x over previous
#include <cuda_runtime.h>
#include <cstdint>

#define FH   45
#define FW   80
#define CC   64
#define BB   16
#define NN   2784
#define JOUT 75
#define JP   80          // P padded j-dim (20 float4)
#define ODIM 77

__device__ float  g_WW[FH * CC * JP];
__device__ float  g_Bh[FH * JP];
__device__ float4 g_P[BB * FH * FW * (JP/4)];
__device__ int    g_off[NN * FH];    // compacted valid offsets per anchor
__device__ int    g_cnt[NN];         // valid count per anchor

// ---------- f32x2 helpers (sm_103a packed fp32) ----------
__device__ __forceinline__ unsigned long long pack2(float a, float b) {
    unsigned long long r;
    asm("mov.b64 %0, {%1, %2};" : "=l"(r) : "f"(a), "f"(b));
    return r;
}
__device__ __forceinline__ void unpack2(unsigned long long v, float& a, float& b) {
    asm("mov.b64 {%0, %1}, %2;" : "=f"(a), "=f"(b) : "l"(v));
}
__device__ __forceinline__ unsigned long long fma2(unsigned long long a,
                                                   unsigned long long b,
                                                   unsigned long long c) {
    unsigned long long r;
    asm("fma.rn.f32x2 %0, %1, %2, %3;" : "=l"(r) : "l"(a), "l"(b), "l"(c));
    return r;
}

// ---------------------------------------------------------------------------
// k1: weight fold, grid (FH, 9), block (20, 16) = 320 thr.
//  blockIdx.y 0..7: 10-j-col slice. Block loads sW[64][10] (its cols only)
//  + full conv_w (float4); each thread produces 2 ci rows for its j.
//  blockIdx.y == 8: anchor compaction (one thread per anchor).
// ---------------------------------------------------------------------------
__global__ void k_prep_all(const float* __restrict__ conv_w, const float* __restrict__ conv_b,
                           const float* __restrict__ cls_w,  const float* __restrict__ reg_w,
                           const int* __restrict__ cut_xs,
                           const unsigned char* __restrict__ invalid) {
    int tx = threadIdx.x;            // 0..19
    int ty = threadIdx.y;            // 0..15
    int tid = ty * 20 + tx;          // 0..319

    if (blockIdx.y == 8) {
        int n = blockIdx.x * 320 + tid;
        if (n >= NN) return;
        const int* cx = cut_xs + n * FH;
        const unsigned char* iv = invalid + n * FH;
        int c = 0;
        int* on = g_off + n * FH;
#pragma unroll 9
        for (int h = 0; h < FH; h++) {
            int xv = cx[h];
            xv = min(max(xv, 0), FW - 1);
            if (!iv[h]) on[c++] = (h * FW + xv) * (JP / 4);
        }
        g_cnt[n] = c;
        return;
    }

    int h  = blockIdx.x;
    int jq = blockIdx.y;             // j-slice 0..7
    __shared__ float sW[CC][10];     // Wcat[o][j-slice]
    __shared__ float sc[CC][CC];     // conv_w[o][ci]
    __shared__ float scb[CC];        // conv_b

    {
        const float4* cw4 = (const float4*)conv_w;
        float4* sc4 = (float4*)&sc[0][0];
        for (int i = tid; i < 1024; i += 320) sc4[i] = cw4[i];
        if (tid < CC) scb[tid] = conv_b[tid];
    }
    for (int t = tid; t < CC * 10; t += 320) {
        int o = t / 10, jj = t - o * 10;
        int j = jq * 10 + jj;
        float v = 0.f;
        if (j < 2)          v = cls_w[(o * FH + h) * 2 + j];
        else if (j < JOUT)  v = reg_w[(o * FH + h) * 73 + (j - 2)];
        sW[o][jj] = v;
    }
    __syncthreads();

    int jx = tid % 10;               // j within slice
    int ci = (tid / 10) * 2;         // 32 groups of 2 ci
    int j  = jq * 10 + jx;
    unsigned long long acc01 = pack2(0.f, 0.f);
    float accb = 0.f;
    bool do_b = (ci == 0);
#pragma unroll 8
    for (int o = 0; o < CC; o++) {
        float wv = sW[o][jx];
        unsigned long long pw = pack2(wv, wv);
        acc01 = fma2(*(const unsigned long long*)&sc[o][ci], pw, acc01);
        if (do_b) accb += scb[o] * wv;
    }
    float a0, a1;
    unpack2(acc01, a0, a1);
    g_WW[(h * CC + ci + 0) * JP + j] = a0;
    g_WW[(h * CC + ci + 1) * JP + j] = a1;
    if (do_b) g_Bh[h * JP + j] = accb;
}

// ---------------------------------------------------------------------------
// k2: P[b,h,w,j] = sum_ci x[b,ci,h,w]*WW[ci,h,j] + Bh[h,j]   (f32x2 packed)
// block (20,16): 4j x 5w tile per thread. grid (FH, BB). float4 smem fills.
// ---------------------------------------------------------------------------
__global__ void k_pcompute(const float* __restrict__ x) {
    int h = blockIdx.x, b = blockIdx.y;
    __shared__ float sx[CC][FW];
    __shared__ float sw[CC][JP];
    int tid = threadIdx.y * 20 + threadIdx.x;   // 0..319

    {
        const float4* xb4  = (const float4*)(x + ((size_t)(b * CC) * FH + h) * FW);
        const float4* ww4  = (const float4*)(g_WW + h * CC * JP);
        float4* sx4 = (float4*)&sx[0][0];
        float4* sw4 = (float4*)&sw[0][0];
#pragma unroll
        for (int i = tid; i < CC * FW / 4; i += 320) {
            int ci = i / 20, w4 = i - ci * 20;
            sx4[i] = xb4[(size_t)ci * (FH * FW / 4) + w4];
            sw4[i] = ww4[i];
        }
    }
    __syncthreads();

    int j0 = threadIdx.x * 4;   // 20*4 = 80 j
    int w0 = threadIdx.y * 5;   // 16*5 = 80 w
    unsigned long long acc0[5], acc1[5];
    unsigned long long z = pack2(0.f, 0.f);
#pragma unroll
    for (int v = 0; v < 5; v++) { acc0[v] = z; acc1[v] = z; }

#pragma unroll 4
    for (int ci = 0; ci < CC; ci++) {
        unsigned long long wa = *(const unsigned long long*)&sw[ci][j0];
        unsigned long long wb = *(const unsigned long long*)&sw[ci][j0 + 2];
#pragma unroll
        for (int v = 0; v < 5; v++) {
            float xs = sx[ci][w0 + v];
            unsigned long long xv = pack2(xs, xs);
            acc0[v] = fma2(xv, wa, acc0[v]);
            acc1[v] = fma2(xv, wb, acc1[v]);
        }
    }

    float4 bh = *(const float4*)&g_Bh[h * JP + j0];
    float* Pp = (float*)g_P + (size_t)((b * FH + h) * FW) * JP;
#pragma unroll
    for (int v = 0; v < 5; v++) {
        float4 r;
        float p0, p1;
        unpack2(acc0[v], p0, p1); r.x = p0 + bh.x; r.y = p1 + bh.y;
        unpack2(acc1[v], p0, p1); r.z = p0 + bh.z; r.w = p1 + bh.w;
        *(float4*)&Pp[(w0 + v) * JP + j0] = r;
    }
}

// ---------------------------------------------------------------------------
// k3: direct L2 gather, 2 batch-images per block (b, b+8), smem-staged
// float4-coalesced epilogue. block (19,16). grid (NN/16, BB/2).
// ---------------------------------------------------------------------------
__global__ void __launch_bounds__(304, 4)
k_gather(const float* __restrict__ cls_b, const float* __restrict__ reg_b,
         const float* __restrict__ anchors,
         float* __restrict__ out) {
    int n0 = blockIdx.x * 16;
    int b0 = blockIdx.y;           // 0..7
    int b1 = b0 + 8;
    __shared__ int   offs[16][FH];
    __shared__ int   cnt[16];
    __shared__ float san[16 * ODIM];        // anchors tile (1232 floats)
    __shared__ float sout[2][16 * ODIM];    // output tiles

    int tx  = threadIdx.x;      // 0..18
    int a   = threadIdx.y;      // 0..15
    int tid = a * 19 + tx;
    for (int t = tid; t < 16 * FH; t += 304) {
        int aa = t / FH, hh = t - aa * FH;
        offs[aa][hh] = g_off[(n0 + aa) * FH + hh];
    }
    if (tid < 16) cnt[tid] = g_cnt[n0 + tid];
    {
        const float4* an4 = (const float4*)(anchors + (size_t)n0 * ODIM);
        float4* s4 = (float4*)san;
        for (int i = tid; i < 16 * ODIM / 4; i += 304) s4[i] = an4[i];
    }
    __syncthreads();

    const float4* Pb0 = g_P + (size_t)b0 * FH * FW * (JP / 4);
    const float4* Pb1 = g_P + (size_t)b1 * FH * FW * (JP / 4);

    int jb = tx * 4;
    float bias[4];
#pragma unroll
    for (int u = 0; u < 4; u++) {
        int j = jb + u;
        bias[u] = (j < 2) ? cls_b[j] : ((j < JOUT) ? reg_b[j - 2] : 0.f);
    }
    float av0[4], av1[4];
#pragma unroll
    for (int u = 0; u < 4; u++) { av0[u] = bias[u]; av1[u] = bias[u]; }

    int c = cnt[a];
    int i = 0;
    for (; i + 4 <= c; i += 4) {
        int o0 = offs[a][i + 0], o1 = offs[a][i + 1];
        int o2 = offs[a][i + 2], o3 = offs[a][i + 3];
        float4 p0 = Pb0[o0 + tx];
        float4 p1 = Pb0[o1 + tx];
        float4 p2 = Pb0[o2 + tx];
        float4 p3 = Pb0[o3 + tx];
        float4 q0 = Pb1[o0 + tx];
        float4 q1 = Pb1[o1 + tx];
        float4 q2 = Pb1[o2 + tx];
        float4 q3 = Pb1[o3 + tx];
        av0[0] += (p0.x + p1.x) + (p2.x + p3.x);
        av0[1] += (p0.y + p1.y) + (p2.y + p3.y);
        av0[2] += (p0.z + p1.z) + (p2.z + p3.z);
        av0[3] += (p0.w + p1.w) + (p2.w + p3.w);
        av1[0] += (q0.x + q1.x) + (q2.x + q3.x);
        av1[1] += (q0.y + q1.y) + (q2.y + q3.y);
        av1[2] += (q0.z + q1.z) + (q2.z + q3.z);
        av1[3] += (q0.w + q1.w) + (q2.w + q3.w);
    }
    for (; i < c; i++) {
        int o = offs[a][i];
        float4 p = Pb0[o + tx];
        float4 q = Pb1[o + tx];
        av0[0] += p.x; av0[1] += p.y; av0[2] += p.z; av0[3] += p.w;
        av1[0] += q.x; av1[1] += q.y; av1[2] += q.z; av1[3] += q.w;
    }

    // ---- stage epilogue into smem in final out-layout ----
    int abase = a * ODIM;
#pragma unroll
    for (int s = 0; s < 2; s++) {
        const float* av = s ? av1 : av0;
#pragma unroll
        for (int u = 0; u < 4; u++) {
            int j = jb + u;
            if (j < 2)          sout[s][abase + j]     = av[u];
            else if (j < JOUT)  sout[s][abase + j + 2] = san[abase + j + 2] + av[u];
        }
        if (tx == 0) {
            sout[s][abase + 2] = san[abase + 2];
            sout[s][abase + 3] = san[abase + 3];
        }
    }
    __syncthreads();

    // ---- coalesced float4 copy to gmem ----
    {
        float4* o4 = (float4*)(out + ((size_t)b0 * NN + n0) * ODIM);
        const float4* s4 = (const float4*)sout[0];
        for (int i2 = tid; i2 < 16 * ODIM / 4; i2 += 304) o4[i2] = s4[i2];
    }
    {
        float4* o4 = (float4*)(out + ((size_t)b1 * NN + n0) * ODIM);
        const float4* s4 = (const float4*)sout[1];
        for (int i2 = tid; i2 < 16 * ODIM / 4; i2 += 304) o4[i2] = s4[i2];
    }
}

// ---------------------------------------------------------------------------
extern "C" void kernel_launch(void* const* d_in, const int* in_sizes, int n_in,
                              void* d_out, int out_size) {
    const float* x       = (const float*)d_in[0];
    const float* conv_w  = (const float*)d_in[1];
    const float* conv_b  = (const float*)d_in[2];
    const float* cls_w   = (const float*)d_in[3];
    const float* cls_b   = (const float*)d_in[4];
    const float* reg_w   = (const float*)d_in[5];
    const float* reg_b   = (const float*)d_in[6];
    const float* anchors = (const float*)d_in[7];
    const int*   cut_xs  = (const int*)d_in[8];
    const unsigned char* invalid = (const unsigned char*)d_in[9];
    float* out = (float*)d_out;

    k_prep_all<<<dim3(FH, 9),      dim3(20, 16)>>>(conv_w, conv_b, cls_w, reg_w, cut_xs, invalid);
    k_pcompute<<<dim3(FH, BB),     dim3(20, 16)>>>(x);
    k_gather  <<<dim3(NN / 16, 8), dim3(19, 16)>>>(cls_b, reg_b, anchors, out);
}